// round 9
// baseline (speedup 1.0000x reference)
#include <cuda_runtime.h>
#include <cstdint>

#define N_TOKENS   262144
#define N_EXPERTS  256
#define TOP_K      8

#define LOGITS_ELEMS   ((size_t)N_TOKENS * N_EXPERTS)   // 67108864
#define TOPK_ELEMS     ((size_t)N_TOKENS * TOP_K)       // 2097152

#define BLOCKS   888           // 148 SMs * 6 blocks -> single clean wave
#define THREADS  256
#define WARPS_PER_BLOCK (THREADS / 32)
#define MAX_SURV 16

// float -> order-preserving uint key (finite floats)
__device__ __forceinline__ unsigned f2key(float f) {
    unsigned u = __float_as_uint(f);
    return u ^ (0x80000000u | (unsigned)((int)u >> 31));
}
__device__ __forceinline__ float key2f(unsigned k) {
    unsigned u = (k & 0x80000000u) ? (k ^ 0x80000000u) : ~k;
    return __uint_as_float(u);
}
// packed sort key: (value asc-key << 8) | (255 - idx)  -> max == (value desc, idx asc)
__device__ __forceinline__ unsigned long long packkey(float v, unsigned idx) {
    return (((unsigned long long)f2key(v)) << 8) | (unsigned long long)(255u - idx);
}

__global__ void zero_hist_kernel(float* __restrict__ hist_out) {
    hist_out[threadIdx.x] = 0.0f;
}

__global__ void __launch_bounds__(THREADS, 6)
moe_router_kernel(const float* __restrict__ logits, float* __restrict__ out) {
    __shared__ int   s_hist[N_EXPERTS];
    __shared__ uint2 s_surv[WARPS_PER_BLOCK][MAX_SURV];

    const int tid  = threadIdx.x;
    const int lane = tid & 31;
    const int wip  = tid >> 5;
    const int warp_global = blockIdx.x * WARPS_PER_BLOCK + wip;
    const int n_warps     = BLOCKS * WARPS_PER_BLOCK;

    s_hist[tid] = 0;
    __syncthreads();

    float* __restrict__ outW = out + LOGITS_ELEMS;
    float* __restrict__ outI = outW + TOPK_ELEMS;
    uint2* buf = s_surv[wip];

    for (int tok = warp_global; tok < N_TOKENS; tok += n_warps) {
        const float4* row = (const float4*)(logits + (size_t)tok * N_EXPERTS);
        // FULLY COALESCED: lane L owns indices [4L,4L+4) and [128+4L,128+4L+4).
        // Index-order tie-break is handled by packed keys (true idx embedded),
        // so lane order need not match index order.
        float4 a = row[lane];
        float4 b = row[lane + 32];

        float4* orow = (float4*)(out + (size_t)tok * N_EXPERTS);
        orow[lane]      = a;   // pass-through logits copy (reuse loaded data)
        orow[lane + 32] = b;

        float f0=a.x, f1=a.y, f2=a.z, f3=a.w, f4=b.x, f5=b.y, f6=b.z, f7=b.w;
        const unsigned ia = 4u * lane;        // base idx of a.{x,y,z,w}
        const unsigned ib = 128u + 4u * lane; // base idx of b.{x,y,z,w}

        // per-lane max (7 FMNMX)
        float m = fmaxf(fmaxf(fmaxf(f0,f1), fmaxf(f2,f3)),
                        fmaxf(fmaxf(f4,f5), fmaxf(f6,f7)));

        // T0 = ~8th-largest of the 32 lane maxes (lower bound of the global
        // 8th-largest: >=8 zeroed lane-maxes are >= final g). Duplicate maxes
        // zero together -> T0 only shrinks (still a valid lower bound).
        unsigned u = f2key(m);
        unsigned g0 = 0, g = 0;
        #pragma unroll
        for (int r = 0; r < TOP_K; r++) {
            g = __reduce_max_sync(0xffffffffu, u);
            if (r == 0) g0 = g;          // global max key
            u = (u == g) ? 0u : u;
        }
        float T0f = key2f(g);

        // survivor predicates (v >= T0f)
        bool p0=f0>=T0f, p1=f1>=T0f, p2=f2>=T0f, p3=f3>=T0f;
        bool p4=f4>=T0f, p5=f5>=T0f, p6=f6>=T0f, p7=f7>=T0f;
        int cnt = (int)p0+(int)p1+(int)p2+(int)p3+(int)p4+(int)p5+(int)p6+(int)p7;

        // inclusive prefix scan over lanes
        int pfx = cnt;
        #pragma unroll
        for (int d = 1; d < 32; d <<= 1) {
            int t = __shfl_up_sync(0xffffffffu, pfx, d);
            if (lane >= d) pfx += t;
        }
        int total = __shfl_sync(0xffffffffu, pfx, 31);
        int base  = pfx - cnt;

        if (total <= MAX_SURV && total >= TOP_K) {
            // ---- fast path: compact survivors to smem (any order is fine) ----
            int c = base;
            if (p0) buf[c++] = make_uint2(__float_as_uint(f0), ia + 0u);
            if (p1) buf[c++] = make_uint2(__float_as_uint(f1), ia + 1u);
            if (p2) buf[c++] = make_uint2(__float_as_uint(f2), ia + 2u);
            if (p3) buf[c++] = make_uint2(__float_as_uint(f3), ia + 3u);
            if (p4) buf[c++] = make_uint2(__float_as_uint(f4), ib + 0u);
            if (p5) buf[c++] = make_uint2(__float_as_uint(f5), ib + 1u);
            if (p6) buf[c++] = make_uint2(__float_as_uint(f6), ib + 2u);
            if (p7) buf[c++] = make_uint2(__float_as_uint(f7), ib + 3u);
            __syncwarp();

            // lanes 0..total-1 each own one survivor; rank by (value desc, idx asc)
            uint2 sv2  = buf[lane & (MAX_SURV - 1)];
            bool valid = lane < total;
            float sval = __uint_as_float(sv2.x);
            unsigned sidx = sv2.y;
            unsigned long long kk = valid ? packkey(sval, sidx) : 0ull;
            int rank = 0;
            #pragma unroll
            for (int d = 1; d < MAX_SURV; d++) {
                unsigned long long ok = __shfl_xor_sync(0xffffffffu, kk, d, MAX_SURV);
                rank += (ok > kk);
            }

            bool win8 = valid && (rank < TOP_K);
            float vmax = key2f(g0);
            float ex = win8 ? __expf(sval - vmax) : 0.0f;
            float s = ex;
            #pragma unroll
            for (int d = 1; d < MAX_SURV; d <<= 1)
                s += __shfl_xor_sync(0xffffffffu, s, d, MAX_SURV);

            if (win8) {
                outW[(size_t)tok * TOP_K + rank] = __fdividef(ex, s);
                outI[(size_t)tok * TOP_K + rank] = (float)sidx;
                atomicAdd(&s_hist[sidx], 1);
            }
            __syncwarp();   // protect buf across loop iterations
        } else {
            // ---- fallback (rare, warp-uniform): exact 8-round selection over
            // packed keys -> (value desc, idx asc), mapping-independent ----
            unsigned long long k64[8];
            k64[0]=packkey(f0, ia+0u); k64[1]=packkey(f1, ia+1u);
            k64[2]=packkey(f2, ia+2u); k64[3]=packkey(f3, ia+3u);
            k64[4]=packkey(f4, ib+0u); k64[5]=packkey(f5, ib+1u);
            k64[6]=packkey(f6, ib+2u); k64[7]=packkey(f7, ib+3u);

            unsigned long long mykey = 0ull;
            #pragma unroll
            for (int r = 0; r < TOP_K; r++) {
                unsigned long long lm = k64[0];
                #pragma unroll
                for (int j = 1; j < 8; j++) lm = (k64[j] > lm) ? k64[j] : lm;
                unsigned long long gm = lm;
                #pragma unroll
                for (int d = 1; d < 32; d <<= 1) {
                    unsigned long long o = __shfl_xor_sync(0xffffffffu, gm, d);
                    gm = (o > gm) ? o : gm;
                }
                if (lane == r) mykey = gm;
                // unique winner lane (idx embedded in key): remove the element
                #pragma unroll
                for (int j = 0; j < 8; j++) if (k64[j] == gm) k64[j] = 0ull;
            }

            float vmax  = key2f((unsigned)(__shfl_sync(0xffffffffu, mykey, 0) >> 8));
            unsigned myk32 = (unsigned)(mykey >> 8);
            unsigned myidx = 255u - (unsigned)(mykey & 0xFFull);
            float myval = (lane < TOP_K) ? key2f(myk32) : vmax;
            float e = __expf(myval - vmax);
            float s = e;
            s += __shfl_xor_sync(0xffffffffu, s, 1);
            s += __shfl_xor_sync(0xffffffffu, s, 2);
            s += __shfl_xor_sync(0xffffffffu, s, 4);   // sums within 8-lane groups

            if (lane < TOP_K) {
                outW[(size_t)tok * TOP_K + lane] = __fdividef(e, s);
                outI[(size_t)tok * TOP_K + lane] = (float)myidx;
                atomicAdd(&s_hist[myidx], 1);
            }
        }
    }

    __syncthreads();
    float* __restrict__ outH = out + LOGITS_ELEMS + 2 * TOPK_ELEMS;
    int c = s_hist[tid];
    if (c > 0) atomicAdd(&outH[tid], (float)c);
}

extern "C" void kernel_launch(void* const* d_in, const int* in_sizes, int n_in,
                              void* d_out, int out_size) {
    const float* logits = (const float*)d_in[0];
    float* out = (float*)d_out;

    float* hist_region = out + LOGITS_ELEMS + 2 * TOPK_ELEMS;
    zero_hist_kernel<<<1, N_EXPERTS>>>(hist_region);
    moe_router_kernel<<<BLOCKS, THREADS>>>(logits, out);
}